// round 12
// baseline (speedup 1.0000x reference)
#include <cuda_runtime.h>
#include <cstddef>
#include <cstdint>

// DCTFeatureModel — collapsed linear model:
// feat[b,s,o] = sum_{t,ij} xc[b,s,t,ij] * Veff[s,o,t,ij] + bias[s,o]
//   xc[b,s,t,ij]    = sum_c x[b, s*256 + c*32 + t, ij]
//   Veff[s,o,t,i,j] = (1/8) sum_{f,p,q} Ct[f,t] Cs[p,i] Cs[q,j] W[s,o,f,p,q]
// out[b, s*64+o] = leaky_relu(feat)
//
// R12: same proven main instruction mix; tile reshape KSPLIT 16->8,
// b-tile 64->32 (grid still 512, occ 4). Halves g_part traffic (8MB->4MB
// round trip), halves accumulator registers, epi loop 16->8.

#define NSW 2
#define NF 64
#define KSPLIT 8
#define MTILES 32

__device__ __align__(16) float g_veff[NSW * 32 * 64 * 64];        // [s][t][ij][o], 1 MB
__device__ __align__(16) float g_part[KSPLIT * 1024 * NSW * NF];  // 4 MB

typedef unsigned long long u64;

__device__ __forceinline__ u64 pk2(float a, float b) {
    u64 r; asm("mov.b64 %0,{%1,%2};" : "=l"(r) : "f"(a), "f"(b)); return r;
}
__device__ __forceinline__ float2 up2(u64 a) {
    float2 v; asm("mov.b64 {%0,%1},%2;" : "=f"(v.x), "=f"(v.y) : "l"(a)); return v;
}
__device__ __forceinline__ void fma2(u64& d, u64 a, u64 b) {
    asm("fma.rn.f32x2 %0,%1,%2,%0;" : "+l"(d) : "l"(a), "l"(b));
}
__device__ __forceinline__ u64 add2(u64 a, u64 b) {
    u64 r; asm("add.rn.f32x2 %0,%1,%2;" : "=l"(r) : "l"(a), "l"(b)); return r;
}

// ---------------------------------------------------------------------------
// prep: R4-exact. one CTA per (s,o), 128 CTAs, register-blocked stages.
// ---------------------------------------------------------------------------
__global__ void __launch_bounds__(256) prep_kernel(const float* __restrict__ W) {
    __shared__ __align__(16) float A[2048];
    __shared__ __align__(16) float Bf[2048];
    __shared__ __align__(16) float B2[2048];
    __shared__ __align__(16) float Ct[1024];
    __shared__ __align__(16) float Cs[64];
    __shared__ __align__(16) float Cst[64];

    const int tid = threadIdx.x;
    const int s = blockIdx.x >> 6;
    const int o = blockIdx.x & 63;

#pragma unroll
    for (int r = 0; r < 4; ++r) {
        int idx = tid + 256 * r;
        int t = idx >> 5, f = idx & 31;
        Ct[idx] = 2.0f * cospif((float)((2 * t + 1) * f) / 64.0f);
    }
    if (tid < 64) {
        int i = tid >> 3, p = tid & 7;
        Cs[tid] = 2.0f * cospif((float)((2 * i + 1) * p) / 16.0f);
    } else if (tid < 128) {
        int idx = tid - 64;
        int q = idx >> 3, j = idx & 7;
        Cst[idx] = 2.0f * cospif((float)((2 * j + 1) * q) / 16.0f);
    }
    {
        const float4* Wso = (const float4*)(W + ((size_t)(s * 64 + o) << 11));
        ((float4*)A)[tid] = Wso[tid];
        ((float4*)A)[tid + 256] = Wso[tid + 256];
    }
    __syncthreads();

    const int a = tid >> 4;
    const int t0 = 2 * a, t1 = 2 * a + 1;
    const int g16 = tid & 15;

    // stage 1: f -> t, tile 2t x 4pq
    {
        u64 ac00 = 0, ac01 = 0, ac10 = 0, ac11 = 0;
#pragma unroll
        for (int f = 0; f < 32; ++f) {
            float4 av = ((const float4*)A)[f * 16 + g16];
            u64 a01 = pk2(av.x, av.y), a23 = pk2(av.z, av.w);
            u64 w0 = pk2(Ct[t0 * 32 + f], Ct[t0 * 32 + f]);
            u64 w1 = pk2(Ct[t1 * 32 + f], Ct[t1 * 32 + f]);
            fma2(ac00, a01, w0); fma2(ac01, a23, w0);
            fma2(ac10, a01, w1); fma2(ac11, a23, w1);
        }
        float2 v0 = up2(ac00), v1 = up2(ac01), v2 = up2(ac10), v3 = up2(ac11);
        *(float4*)&Bf[t0 * 64 + 4 * g16] = make_float4(v0.x, v0.y, v1.x, v1.y);
        *(float4*)&Bf[t1 * 64 + 4 * g16] = make_float4(v2.x, v2.y, v3.x, v3.y);
    }
    __syncthreads();

    // stage 2: p -> i, tile 2t x i x 4q
    const int i8 = (tid >> 1) & 7;
    const int qg = tid & 1;
    {
        u64 ac00 = 0, ac01 = 0, ac10 = 0, ac11 = 0;
#pragma unroll
        for (int p = 0; p < 8; ++p) {
            float cs = Cs[i8 * 8 + p];
            u64 w = pk2(cs, cs);
            float4 b0 = *(const float4*)&Bf[t0 * 64 + p * 8 + 4 * qg];
            float4 b1 = *(const float4*)&Bf[t1 * 64 + p * 8 + 4 * qg];
            fma2(ac00, pk2(b0.x, b0.y), w); fma2(ac01, pk2(b0.z, b0.w), w);
            fma2(ac10, pk2(b1.x, b1.y), w); fma2(ac11, pk2(b1.z, b1.w), w);
        }
        float2 v0 = up2(ac00), v1 = up2(ac01), v2 = up2(ac10), v3 = up2(ac11);
        *(float4*)&B2[t0 * 64 + i8 * 8 + 4 * qg] = make_float4(v0.x, v0.y, v1.x, v1.y);
        *(float4*)&B2[t1 * 64 + i8 * 8 + 4 * qg] = make_float4(v2.x, v2.y, v3.x, v3.y);
    }
    __syncthreads();

    // stage 3: q -> j, scale 1/8, scatter
    {
        const int jg = qg;
        float4 r0a = *(const float4*)&B2[t0 * 64 + i8 * 8];
        float4 r0b = *(const float4*)&B2[t0 * 64 + i8 * 8 + 4];
        float4 r1a = *(const float4*)&B2[t1 * 64 + i8 * 8];
        float4 r1b = *(const float4*)&B2[t1 * 64 + i8 * 8 + 4];
        float b0q[8] = {r0a.x, r0a.y, r0a.z, r0a.w, r0b.x, r0b.y, r0b.z, r0b.w};
        float b1q[8] = {r1a.x, r1a.y, r1a.z, r1a.w, r1b.x, r1b.y, r1b.z, r1b.w};
        u64 ac[4] = {};
#pragma unroll
        for (int q = 0; q < 8; ++q) {
            float4 cj = *(const float4*)&Cst[q * 8 + 4 * jg];
            u64 bp = pk2(b0q[q], b1q[q]);
            fma2(ac[0], bp, pk2(cj.x, cj.x));
            fma2(ac[1], bp, pk2(cj.y, cj.y));
            fma2(ac[2], bp, pk2(cj.z, cj.z));
            fma2(ac[3], bp, pk2(cj.w, cj.w));
        }
        float* base0 = g_veff + (((size_t)(s * 32 + t0) << 6) + i8 * 8 + 4 * jg) * 64 + o;
        float* base1 = g_veff + (((size_t)(s * 32 + t1) << 6) + i8 * 8 + 4 * jg) * 64 + o;
#pragma unroll
        for (int j = 0; j < 4; ++j) {
            float2 v = up2(ac[j]);
            base0[j * 64] = 0.125f * v.x;
            base1[j * 64] = 0.125f * v.y;
        }
    }
}

// ---------------------------------------------------------------------------
// main: 512 CTAs x 256 thr, occ 4. CTA = 32b x 64o, K=256 (4 t's, 8 phases).
// Same load map / ws layout / COMP pattern as the proven R4 core; thread
// microtile 2b x 4o (acc = 4 u64).
// ---------------------------------------------------------------------------
__global__ void __launch_bounds__(256, 4) main_kernel(const float* __restrict__ x) {
    __shared__ __align__(16) float xs[2][32][34];  // [buf][ij][b], pad 2
    __shared__ __align__(16) float ws[2][32][64];  // [buf][ij][o]

    const int tid = threadIdx.x;
    const int bx = blockIdx.x;
    const int ks = bx & 7;            // 8 K-slices of 4 t's
    const int mt = (bx >> 3) & 31;    // 32 b-tiles of 32
    const int s = bx >> 8;

    const int ijp = tid & 15, bb = tid >> 4;  // load map: ij = 2ijp(+1), b = bb*2+u
    const int tx = tid & 15, ty = tid >> 4;   // compute map: o = 4tx.., b = 2ty..

    const float* xb = x + (size_t)(mt * 32 + bb * 2) * 32768 + (size_t)s * 16384 + 2 * ijp;

    u64 acc[4] = {};   // acc[j]: o = 4tx+j, packs b = (2ty, 2ty+1)
    u64 xr[8];
    float4 wr0, wr1;

#define PH_T(ph) (ks * 4 + ((ph) >> 1))
#define PH_OFF(ph) ((size_t)(PH_T(ph)) * 64 + ((ph) & 1) * 32)

#define LDG_U(ph, u)                                                          \
    do {                                                                      \
        const u64* p = (const u64*)(xb + (size_t)(u) * 32768 + PH_OFF(ph));   \
        _Pragma("unroll") for (int c = 0; c < 8; ++c) xr[c] = __ldcs(p + c * 1024); \
    } while (0)

#define STS_U(buf, u)                                                         \
    do {                                                                      \
        u64 s0 = add2(add2(xr[0], xr[1]), add2(xr[2], xr[3]));                \
        u64 s1 = add2(add2(xr[4], xr[5]), add2(xr[6], xr[7]));                \
        float2 v = up2(add2(s0, s1));                                         \
        xs[buf][2 * ijp][bb * 2 + (u)] = v.x;                                 \
        xs[buf][2 * ijp + 1][bb * 2 + (u)] = v.y;                             \
    } while (0)

#define LDG_W(ph)                                                             \
    do {                                                                      \
        const float4* wp = (const float4*)(g_veff +                          \
            (((size_t)s * 32 + PH_T(ph)) * 64 + ((ph) & 1) * 32) * 64);       \
        wr0 = wp[tid]; wr1 = wp[tid + 256];                                   \
    } while (0)

#define STS_W(buf)                                                            \
    do {                                                                      \
        float4* wd = (float4*)&ws[buf][0][0];                                 \
        wd[tid] = wr0; wd[tid + 256] = wr1;                                   \
    } while (0)

#define COMP8(buf, k0)                                                        \
    do {                                                                      \
        _Pragma("unroll") for (int k = (k0); k < (k0) + 8; ++k) {             \
            u64 xp = *(const u64*)&xs[buf][k][2 * ty];                        \
            float4 wv = *(const float4*)&ws[buf][k][4 * tx];                  \
            fma2(acc[0], xp, pk2(wv.x, wv.x));                                \
            fma2(acc[1], xp, pk2(wv.y, wv.y));                                \
            fma2(acc[2], xp, pk2(wv.z, wv.z));                                \
            fma2(acc[3], xp, pk2(wv.w, wv.w));                                \
        }                                                                     \
    } while (0)

    // prologue: fill buffer 0 with phase 0
    LDG_W(0);
    LDG_U(0, 0); STS_U(0, 0);
    LDG_U(0, 1); STS_U(0, 1);
    STS_W(0);
    __syncthreads();

#pragma unroll
    for (int ph = 0; ph < 8; ++ph) {
        const int buf = ph & 1, nb = buf ^ 1;
        if (ph < 7) {
            LDG_W(ph + 1);
            LDG_U(ph + 1, 0);
            COMP8(buf, 0); COMP8(buf, 8);
            STS_U(nb, 0);
            LDG_U(ph + 1, 1);
            COMP8(buf, 16); COMP8(buf, 24);
            STS_U(nb, 1);
            STS_W(nb);
        } else {
            COMP8(buf, 0); COMP8(buf, 8); COMP8(buf, 16); COMP8(buf, 24);
        }
        __syncthreads();
    }

    // write partials: g_part[ks][b][s*64+o]
    {
        const int b0 = mt * 32 + 2 * ty;
        const int obase = s * 64 + 4 * tx;
        float2 c0 = up2(acc[0]), c1 = up2(acc[1]);
        float2 c2 = up2(acc[2]), c3 = up2(acc[3]);
        float4 r0 = make_float4(c0.x, c1.x, c2.x, c3.x);
        float4 r1 = make_float4(c0.y, c1.y, c2.y, c3.y);
        __stcs((float4*)(g_part + ((size_t)ks << 17) + (size_t)b0 * 128 + obase), r0);
        __stcs((float4*)(g_part + ((size_t)ks << 17) + (size_t)(b0 + 1) * 128 + obase), r1);
    }
}

// ---------------------------------------------------------------------------
// epilogue: sum KSPLIT partials + bias, LeakyReLU
// ---------------------------------------------------------------------------
__global__ void __launch_bounds__(256) epi_kernel(const float* __restrict__ bias,
                                                  float* __restrict__ out) {
    const int i4 = (blockIdx.x * 256 + threadIdx.x) * 4;
    float4 bv = *(const float4*)(bias + (i4 & 127));
    u64 a0 = pk2(bv.x, bv.y), a1 = pk2(bv.z, bv.w);
#pragma unroll
    for (int k = 0; k < KSPLIT; ++k) {
        const ulonglong2* pp = (const ulonglong2*)(g_part + ((size_t)k << 17) + i4);
        ulonglong2 p;
        p.x = __ldcs(&pp->x);
        p.y = __ldcs(&pp->y);
        a0 = add2(a0, p.x);
        a1 = add2(a1, p.y);
    }
    float2 f0 = up2(a0), f1 = up2(a1);
    float4 r;
    r.x = (f0.x >= 0.0f) ? f0.x : 0.02f * f0.x;
    r.y = (f0.y >= 0.0f) ? f0.y : 0.02f * f0.y;
    r.z = (f1.x >= 0.0f) ? f1.x : 0.02f * f1.x;
    r.w = (f1.y >= 0.0f) ? f1.y : 0.02f * f1.y;
    *(float4*)(out + i4) = r;
}

// ---------------------------------------------------------------------------
extern "C" void kernel_launch(void* const* d_in, const int* in_sizes, int n_in,
                              void* d_out, int out_size) {
    const float* x = nullptr;
    const float* W = nullptr;
    const float* bias = nullptr;
    for (int i = 0; i < n_in; ++i) {
        if (in_sizes[i] == 1024 * 512 * 64) x = (const float*)d_in[i];
        else if (in_sizes[i] == NSW * NF * 32 * 64) W = (const float*)d_in[i];
        else if (in_sizes[i] == NSW * NF) bias = (const float*)d_in[i];
    }
    if (!x) x = (const float*)d_in[0];
    if (!W) W = (const float*)d_in[1];
    if (!bias) bias = (const float*)d_in[2];

    prep_kernel<<<NSW * NF, 256>>>(W);
    main_kernel<<<NSW * MTILES * KSPLIT, 256>>>(x);
    epi_kernel<<<(1024 * NSW * NF) / (256 * 4), 256>>>(bias, (float*)d_out);
}

// round 13
// speedup vs baseline: 1.1691x; 1.1691x over previous
#include <cuda_runtime.h>
#include <cstddef>
#include <cstdint>

// DCTFeatureModel — collapsed linear model:
// feat[b,s,o] = sum_{t,ij} xc[b,s,t,ij] * Veff[s,o,t,ij] + bias[s,o]
//   xc[b,s,t,ij]    = sum_c x[b, s*256 + c*32 + t, ij]
//   Veff[s,o,t,i,j] = (1/8) sum_{f,p,q} Ct[f,t] Cs[p,i] Cs[q,j] W[s,o,f,p,q]
// out[b, s*64+o] = leaky_relu(feat)
//
// R13: prep FUSED into main. Each CTA (s,ks,mt) computes its own veff
// sub-slice (2 t's x 4 o's, ~1.5us), publishes via per-(s,ks) flag (16
// arrivals), prefetches its phase-0 x tile BEFORE spinning, then runs the
// R4-exact GEMM. epi separate (DRAM-floor) + resets flags for next replay.

#define NSW 2
#define NF 64
#define KSPLIT 16
#define MTILES 16

__device__ __align__(16) float g_veff[NSW * 32 * 64 * 64];        // [s][t][ij][o], 1 MB
__device__ __align__(16) float g_part[KSPLIT * 1024 * NSW * NF];  // 8 MB
__device__ int g_flag[32];  // per-(s,ks) slice arrival counters; epi resets

typedef unsigned long long u64;

__device__ __forceinline__ u64 pk2(float a, float b) {
    u64 r; asm("mov.b64 %0,{%1,%2};" : "=l"(r) : "f"(a), "f"(b)); return r;
}
__device__ __forceinline__ float2 up2(u64 a) {
    float2 v; asm("mov.b64 {%0,%1},%2;" : "=f"(v.x), "=f"(v.y) : "l"(a)); return v;
}
__device__ __forceinline__ void fma2(u64& d, u64 a, u64 b) {
    asm("fma.rn.f32x2 %0,%1,%2,%0;" : "+l"(d) : "l"(a), "l"(b));
}
__device__ __forceinline__ u64 add2(u64 a, u64 b) {
    u64 r; asm("add.rn.f32x2 %0,%1,%2;" : "=l"(r) : "l"(a), "l"(b)); return r;
}

// ---------------------------------------------------------------------------
// main: 512 CTAs x 256 thr, occ 4.
//   phase A: inline veff prep for (s, t=2ks..2ks+1, o=mt*4..mt*4+4)
//   phase B: R4-exact GEMM (phase-0 x prefetched before the slice spin)
// ---------------------------------------------------------------------------
__global__ void __launch_bounds__(256, 4) main_kernel(
    const float* __restrict__ x, const float* __restrict__ W) {
    __shared__ __align__(16) float xs[2][32][68];  // [buf][ij][b]; aliased as W-staging A
    __shared__ __align__(16) float ws[2][32][64];  // [buf][ij][o]; aliased as W-staging B
    __shared__ __align__(16) float buf1[256];
    __shared__ __align__(16) float buf2[256];
    __shared__ __align__(16) float CtL[64];   // our 2 t-rows: [t01][f]
    __shared__ __align__(16) float CsL[64];   // [i][p]
    __shared__ __align__(16) float CstL[64];  // [q][j]

    const int tid = threadIdx.x;
    const int bx = blockIdx.x;
    const int ks = bx & 15;
    const int mt = (bx >> 4) & 15;
    const int s = bx >> 8;
    const int slice = s * 16 + ks;

    // ======================= phase A: inline veff prep =======================
    {
        // tables (<=1 cospif per thread)
        if (tid < 64) {
            int t01 = tid >> 5, f = tid & 31;
            CtL[tid] = 2.0f * cospif((float)((2 * (ks * 2 + t01) + 1) * f) / 64.0f);
        } else if (tid < 128) {
            int e = tid - 64;
            CsL[e] = 2.0f * cospif((float)((2 * (e >> 3) + 1) * (e & 7)) / 16.0f);
        } else if (tid < 192) {
            int e = tid - 128;  // e = q*8 + j
            CstL[e] = 2.0f * cospif((float)((2 * (e & 7) + 1) * (e >> 3)) / 16.0f);
        }

        // load our 4 o's of W[s] (32 KB): group A = o {0,1}, B = o {2,3}
        const float4* wp = (const float4*)(W + ((size_t)(s * 64 + mt * 4) << 11));
        float4 ra0 = wp[tid], ra1 = wp[tid + 256], ra2 = wp[tid + 512], ra3 = wp[tid + 768];
        float4 rb0 = wp[tid + 1024], rb1 = wp[tid + 1280],
               rb2 = wp[tid + 1536], rb3 = wp[tid + 1792];
        float* WSa = &xs[0][0][0];  // 4096-float staging (xs is dead until GEMM)
        float* WSb = &ws[0][0][0];  // 4096-float staging
        ((float4*)WSa)[tid] = ra0; ((float4*)WSa)[tid + 256] = ra1;
        ((float4*)WSa)[tid + 512] = ra2; ((float4*)WSa)[tid + 768] = ra3;
        ((float4*)WSb)[tid] = rb0; ((float4*)WSb)[tid + 256] = rb1;
        ((float4*)WSb)[tid + 512] = rb2; ((float4*)WSb)[tid + 768] = rb3;
        __syncthreads();

        const int o2 = tid >> 7;          // which o of the pair
        const int t01 = (tid >> 6) & 1;   // which t
        const int pq = tid & 63;
        const int grp = tid & 192;        // o2*128 + t01*64
        const int i3 = (tid >> 3) & 7;    // i (stage2) / i (stage3)
        const int j3 = tid & 7;           // q (stage2) / j (stage3)

#pragma unroll
        for (int og = 0; og < 2; ++og) {
            const float* WS = og ? WSb : WSa;
            // stage 1: f -> t
            float a = 0.0f;
#pragma unroll
            for (int f = 0; f < 32; ++f)
                a = fmaf(CtL[t01 * 32 + f], WS[o2 * 2048 + f * 64 + pq], a);
            buf1[tid] = a;
            __syncthreads();
            // stage 2: p -> i
            float b = 0.0f;
#pragma unroll
            for (int p = 0; p < 8; ++p)
                b = fmaf(CsL[i3 * 8 + p], buf1[grp + p * 8 + j3], b);
            buf2[tid] = b;
            __syncthreads();
            // stage 3: q -> j, scale, store
            float c = 0.0f;
#pragma unroll
            for (int q = 0; q < 8; ++q)
                c = fmaf(CstL[q * 8 + j3], buf2[grp + i3 * 8 + q], c);
            int o = mt * 4 + og * 2 + o2;
            int row = ((s * 32 + ks * 2 + t01) << 6) + i3 * 8 + j3;
            g_veff[(size_t)row * 64 + o] = 0.125f * c;
            __syncthreads();
        }
        __threadfence();
        __syncthreads();
        if (tid == 0) atomicAdd(&g_flag[slice], 1);
    }

    // ======================= phase B: R4-exact GEMM =======================
    const int ijp = tid & 15, bb = tid >> 4;  // load map (coalesced 128B rows)
    const int tx = tid & 15, ty = tid >> 4;   // compute map

    const float* xb = x + (size_t)(mt * 64 + bb * 4) * 32768 + (size_t)s * 16384 + 2 * ijp;

    u64 acc[2][4] = {};
    u64 xr[8];
    float4 wr0, wr1;

#define PH_T(ph) (ks * 2 + ((ph) >> 1))
#define PH_OFF(ph) ((size_t)(PH_T(ph)) * 64 + ((ph) & 1) * 32)

#define LDG_U(ph, u)                                                          \
    do {                                                                      \
        const u64* p = (const u64*)(xb + (size_t)(u) * 32768 + PH_OFF(ph));   \
        _Pragma("unroll") for (int c = 0; c < 8; ++c) xr[c] = __ldcs(p + c * 1024); \
    } while (0)

#define STS_U(buf, u)                                                         \
    do {                                                                      \
        u64 s0 = add2(add2(xr[0], xr[1]), add2(xr[2], xr[3]));                \
        u64 s1 = add2(add2(xr[4], xr[5]), add2(xr[6], xr[7]));                \
        float2 v = up2(add2(s0, s1));                                         \
        xs[buf][2 * ijp][bb * 4 + (u)] = v.x;                                 \
        xs[buf][2 * ijp + 1][bb * 4 + (u)] = v.y;                             \
    } while (0)

#define LDG_W(ph)                                                             \
    do {                                                                      \
        const float4* wp2 = (const float4*)(g_veff +                         \
            (((size_t)s * 32 + PH_T(ph)) * 64 + ((ph) & 1) * 32) * 64);       \
        wr0 = wp2[tid]; wr1 = wp2[tid + 256];                                 \
    } while (0)

#define STS_W(buf)                                                            \
    do {                                                                      \
        float4* wd = (float4*)&ws[buf][0][0];                                 \
        wd[tid] = wr0; wd[tid + 256] = wr1;                                   \
    } while (0)

#define COMP8(buf, k0)                                                        \
    do {                                                                      \
        _Pragma("unroll") for (int k = (k0); k < (k0) + 8; ++k) {             \
            ulonglong2 xp = *(const ulonglong2*)&xs[buf][k][4 * ty];          \
            float4 wv = *(const float4*)&ws[buf][k][4 * tx];                  \
            u64 w0 = pk2(wv.x, wv.x), w1 = pk2(wv.y, wv.y);                   \
            u64 w2 = pk2(wv.z, wv.z), w3 = pk2(wv.w, wv.w);                   \
            fma2(acc[0][0], xp.x, w0); fma2(acc[1][0], xp.y, w0);             \
            fma2(acc[0][1], xp.x, w1); fma2(acc[1][1], xp.y, w1);             \
            fma2(acc[0][2], xp.x, w2); fma2(acc[1][2], xp.y, w2);             \
            fma2(acc[0][3], xp.x, w3); fma2(acc[1][3], xp.y, w3);             \
        }                                                                     \
    } while (0)

    // phase-0 x prefetch + c-reduce into xs[0] BEFORE the slice spin
    LDG_U(0, 0); STS_U(0, 0);
    LDG_U(0, 1); STS_U(0, 1);
    LDG_U(0, 2); STS_U(0, 2);
    LDG_U(0, 3); STS_U(0, 3);

    // wait for our slice's 16 producers
    if (tid == 0) {
        int v;
        do {
            asm volatile("ld.global.acquire.gpu.b32 %0, [%1];"
                         : "=r"(v) : "l"(g_flag + slice) : "memory");
            if (v < 16) __nanosleep(32);
        } while (v < 16);
    }
    __syncthreads();

    LDG_W(0);
    STS_W(0);
    __syncthreads();

#pragma unroll
    for (int ph = 0; ph < 4; ++ph) {
        const int buf = ph & 1, nb = buf ^ 1;
        if (ph < 3) {
            LDG_W(ph + 1);
            LDG_U(ph + 1, 0); COMP8(buf, 0);  STS_U(nb, 0);
            LDG_U(ph + 1, 1); COMP8(buf, 8);  STS_U(nb, 1);
            LDG_U(ph + 1, 2); COMP8(buf, 16); STS_U(nb, 2);
            LDG_U(ph + 1, 3); COMP8(buf, 24); STS_U(nb, 3);
            STS_W(nb);
        } else {
            COMP8(buf, 0); COMP8(buf, 8); COMP8(buf, 16); COMP8(buf, 24);
        }
        __syncthreads();
    }

    // write partials: g_part[ks][b][s*64+o]
    const int b0 = mt * 64 + 4 * ty;
    const int obase = s * 64 + 4 * tx;
#pragma unroll
    for (int p = 0; p < 2; ++p) {
        float2 c0 = up2(acc[p][0]), c1 = up2(acc[p][1]);
        float2 c2 = up2(acc[p][2]), c3 = up2(acc[p][3]);
        float4 r0 = make_float4(c0.x, c1.x, c2.x, c3.x);
        float4 r1 = make_float4(c0.y, c1.y, c2.y, c3.y);
        __stcs((float4*)(g_part + ((size_t)ks << 17) + (size_t)(b0 + 2 * p) * 128 + obase), r0);
        __stcs((float4*)(g_part + ((size_t)ks << 17) + (size_t)(b0 + 2 * p + 1) * 128 + obase), r1);
    }
}

// ---------------------------------------------------------------------------
// epilogue: sum KSPLIT partials + bias, LeakyReLU; resets slice flags.
// ---------------------------------------------------------------------------
__global__ void __launch_bounds__(256) epi_kernel(const float* __restrict__ bias,
                                                  float* __restrict__ out) {
    if (blockIdx.x == 0 && threadIdx.x < 32) g_flag[threadIdx.x] = 0;  // next replay

    const int i4 = (blockIdx.x * 256 + threadIdx.x) * 4;
    float4 bv = *(const float4*)(bias + (i4 & 127));
    u64 a0 = pk2(bv.x, bv.y), a1 = pk2(bv.z, bv.w);
#pragma unroll
    for (int k = 0; k < KSPLIT; ++k) {
        const ulonglong2* pp = (const ulonglong2*)(g_part + ((size_t)k << 17) + i4);
        ulonglong2 p;
        p.x = __ldcs(&pp->x);
        p.y = __ldcs(&pp->y);
        a0 = add2(a0, p.x);
        a1 = add2(a1, p.y);
    }
    float2 f0 = up2(a0), f1 = up2(a1);
    float4 r;
    r.x = (f0.x >= 0.0f) ? f0.x : 0.02f * f0.x;
    r.y = (f0.y >= 0.0f) ? f0.y : 0.02f * f0.y;
    r.z = (f1.x >= 0.0f) ? f1.x : 0.02f * f1.x;
    r.w = (f1.y >= 0.0f) ? f1.y : 0.02f * f1.y;
    *(float4*)(out + i4) = r;
}

// ---------------------------------------------------------------------------
extern "C" void kernel_launch(void* const* d_in, const int* in_sizes, int n_in,
                              void* d_out, int out_size) {
    const float* x = nullptr;
    const float* W = nullptr;
    const float* bias = nullptr;
    for (int i = 0; i < n_in; ++i) {
        if (in_sizes[i] == 1024 * 512 * 64) x = (const float*)d_in[i];
        else if (in_sizes[i] == NSW * NF * 32 * 64) W = (const float*)d_in[i];
        else if (in_sizes[i] == NSW * NF) bias = (const float*)d_in[i];
    }
    if (!x) x = (const float*)d_in[0];
    if (!W) W = (const float*)d_in[1];
    if (!bias) bias = (const float*)d_in[2];

    main_kernel<<<NSW * MTILES * KSPLIT, 256>>>(x, W);
    epi_kernel<<<(1024 * NSW * NF) / (256 * 4), 256>>>(bias, (float*)d_out);
}